// round 15
// baseline (speedup 1.0000x reference)
#include <cuda_runtime.h>
#include <cuda_fp16.h>
#include <math.h>
#include <cstdint>

#define DD 1280
#define NH 8
#define HDIM 160
#define RK 4
#define NB 2
#define SEQ 2048
#define NTOK (NB*SEQ)

// ---- scratch (static __device__ arrays; no allocation) ----
__device__ float g_down[4][RK*DD];
__device__ float g_up[4][RK*DD];
__device__ __half g_Whi[4][DD*DD];
__device__ __half g_Wlo[4][DD*DD];
__device__ __half g_Ah[NTOK*DD];        // x, fp16 hi only
__device__ __half g_Qh[NTOK*DD];
__device__ __half g_Kh[NTOK*DD];
__device__ __half g_Kl[NTOK*DD];
__device__ __half g_Vh[NTOK*DD];
__device__ __half g_Vl[NTOK*DD];
__device__ __half g_AOh[NTOK*DD];

// ============================================================
// helpers (family-portable, sm_80+)
// ============================================================
__device__ __forceinline__ uint32_t smem_u32(const void* p) {
    uint32_t a;
    asm("{ .reg .u64 t; cvta.to.shared.u64 t, %1; cvt.u32.u64 %0, t; }" : "=r"(a) : "l"(p));
    return a;
}
__device__ __forceinline__ void cp16(uint32_t dst, const void* src) {
    asm volatile("cp.async.cg.shared.global [%0], [%1], 16;" :: "r"(dst), "l"(src) : "memory");
}
#define CP_COMMIT() asm volatile("cp.async.commit_group;" ::: "memory")
#define CP_WAIT(n)  asm volatile("cp.async.wait_group %0;" :: "n"(n) : "memory")

__device__ __forceinline__ void ldsm4(uint32_t* r, uint32_t addr) {
    asm volatile("ldmatrix.sync.aligned.m8n8.x4.shared.b16 {%0,%1,%2,%3}, [%4];"
        : "=r"(r[0]), "=r"(r[1]), "=r"(r[2]), "=r"(r[3]) : "r"(addr));
}
__device__ __forceinline__ void ldsm4t(uint32_t* r, uint32_t addr) {
    asm volatile("ldmatrix.sync.aligned.m8n8.x4.trans.shared.b16 {%0,%1,%2,%3}, [%4];"
        : "=r"(r[0]), "=r"(r[1]), "=r"(r[2]), "=r"(r[3]) : "r"(addr));
}
__device__ __forceinline__ void mma16816(float* d, const uint32_t* a, const uint32_t* b) {
    asm volatile(
        "mma.sync.aligned.m16n8k16.row.col.f32.f16.f16.f32 "
        "{%0,%1,%2,%3}, {%4,%5,%6,%7}, {%8,%9}, {%0,%1,%2,%3};"
        : "+f"(d[0]), "+f"(d[1]), "+f"(d[2]), "+f"(d[3])
        : "r"(a[0]), "r"(a[1]), "r"(a[2]), "r"(a[3]), "r"(b[0]), "r"(b[1]));
}
__device__ __forceinline__ float ex2f(float x) {
    float y; asm("ex2.approx.f32 %0, %1;" : "=f"(y) : "f"(x)); return y;
}
__device__ __forceinline__ uint32_t pack2(float a, float b) {
    __half2 v = __floats2half2_rn(a, b);
    return reinterpret_cast<uint32_t&>(v);
}
__device__ __forceinline__ float res_lo(float f) {
    return f - __half2float(__float2half_rn(f));
}

// ============================================================
// Kernel 0: contract palette into down/up vectors for 4 LoRAs
// ============================================================
__global__ void k_downup(const float* __restrict__ pal,
    const float* __restrict__ qd, const float* __restrict__ qu,
    const float* __restrict__ kd, const float* __restrict__ ku,
    const float* __restrict__ vd, const float* __restrict__ vu,
    const float* __restrict__ od, const float* __restrict__ ou)
{
    __shared__ float p[15];
    if (threadIdx.x < 15) p[threadIdx.x] = pal[threadIdx.x];
    __syncthreads();
    int idx = blockIdx.x * blockDim.x + threadIdx.x;
    if (idx >= 8 * RK * DD) return;
    int which = idx / (RK * DD);
    int e = idx - which * (RK * DD);
    const float* srcs[8] = {qd, qu, kd, ku, vd, vu, od, ou};
    const float* s = srcs[which];
    float acc = 0.f;
#pragma unroll
    for (int j = 0; j < 15; j++) acc += p[j] * s[e * 15 + j];
    if (which & 1) g_up[which >> 1][e] = acc;
    else          g_down[which >> 1][e] = acc;
}

// ============================================================
// Kernel 1: W_eff = W + up @ down, written as fp16 hi/lo pair
// ============================================================
__global__ void k_weff(const float* __restrict__ Wq, const float* __restrict__ Wk,
                       const float* __restrict__ Wv, const float* __restrict__ Wo)
{
    const int per_w = DD * DD / 4;
    int idx = blockIdx.x * blockDim.x + threadIdx.x;
    if (idx >= 4 * per_w) return;
    int w = idx / per_w;
    int e4 = idx - w * per_w;
    int o = e4 / (DD / 4);
    int i4 = e4 - o * (DD / 4);
    const float* Ws[4] = {Wq, Wk, Wv, Wo};
    float4 acc = reinterpret_cast<const float4*>(Ws[w])[e4];
#pragma unroll
    for (int r = 0; r < RK; r++) {
        float u = g_up[w][o * RK + r];
        float4 d = reinterpret_cast<const float4*>(&g_down[w][r * DD])[i4];
        acc.x += u * d.x; acc.y += u * d.y; acc.z += u * d.z; acc.w += u * d.w;
    }
    float v[4] = {acc.x, acc.y, acc.z, acc.w};
    reinterpret_cast<uint32_t*>(&g_Whi[w][0])[2*e4]   = pack2(v[0], v[1]);
    reinterpret_cast<uint32_t*>(&g_Whi[w][0])[2*e4+1] = pack2(v[2], v[3]);
    reinterpret_cast<uint32_t*>(&g_Wlo[w][0])[2*e4]   = pack2(res_lo(v[0]), res_lo(v[1]));
    reinterpret_cast<uint32_t*>(&g_Wlo[w][0])[2*e4+1] = pack2(res_lo(v[2]), res_lo(v[3]));
}

// ============================================================
// Kernel 1b: fp32 activation -> fp16 hi only
// ============================================================
__global__ void k_cvtA(const float* __restrict__ src)
{
    int i = blockIdx.x * blockDim.x + threadIdx.x;
    if (i >= NTOK * DD / 4) return;
    float4 a = reinterpret_cast<const float4*>(src)[i];
    reinterpret_cast<uint32_t*>(g_Ah)[2*i]   = pack2(a.x, a.y);
    reinterpret_cast<uint32_t*>(g_Ah)[2*i+1] = pack2(a.z, a.w);
}

// ============================================================
// GEMM core: 128x128 CTA tile, BK=32, 4 warps x (64x64 warp
// tile), 128 threads. 2-pass split fp16: C = Ah @ (Wh+Wl)^T.
// 12 ldsm feed 64 MMAs per warp per ks-iter (smem-unbound).
// ============================================================
#define BK 32
#define TSTRIDE 80
#define TILEB (128 * TSTRIDE)
#define STAGEB (3 * TILEB)         // Ah, Wh, Wl
#define GEMM_SMEM (2 * STAGEB)
#define NCHUNK (DD / BK)

struct GemmOut {
    float* Cf; const float* bias;
    __half* Ch; __half* Cl;        // Cl may be null (hi-only output)
};

__device__ __forceinline__ void gemm_body(
    const __half* __restrict__ Ah, const __half* __restrict__ Whi,
    const __half* __restrict__ Wlo,
    const GemmOut& o, size_t tileM, size_t tileN, char* smem)
{
    const uint32_t sbase = smem_u32(smem);
    const int tid = threadIdx.x;
    const int lane = tid & 31, wid = tid >> 5;        // 4 warps
    const int warp_m = (wid & 1) * 64, warp_n = (wid >> 1) * 64;
    const int K = DD, N = DD;

    const __half* srcs[3] = {Ah, Whi, Wlo};

    auto load_stage = [&](int kc, int s) {
        const int kcol = kc * BK;
        uint32_t dst0 = sbase + s * STAGEB;
#pragma unroll
        for (int i = 0; i < 12; i++) {
            int idx = i * 128 + tid;           // 3 tiles x 128 rows x 4 chunks
            int t = idx >> 9;
            int rem = idx & 511;
            int r = rem >> 2, c = rem & 3;
            size_t grow = (t == 0) ? (tileM + r) : (tileN + r);
            const __half* src = srcs[t] + grow * K + kcol + c * 8;
            cp16(dst0 + t * TILEB + r * TSTRIDE + c * 16, src);
        }
        CP_COMMIT();
    };

    float acc[4][8][4];
#pragma unroll
    for (int mf = 0; mf < 4; mf++)
#pragma unroll
        for (int nf = 0; nf < 8; nf++)
#pragma unroll
            for (int j = 0; j < 4; j++) acc[mf][nf][j] = 0.f;

    load_stage(0, 0);

    const int a_row = warp_m + ((lane >> 3) & 1) * 8 + (lane & 7);
    const uint32_t a_off = (uint32_t)(a_row * TSTRIDE + (lane >> 4) * 16);
    const int b_row = warp_n + ((lane >> 4) & 1) * 8 + (lane & 7);
    const uint32_t b_off = (uint32_t)(b_row * TSTRIDE + ((lane >> 3) & 1) * 16);

    for (int kc = 0; kc < NCHUNK; kc++) {
        const int s = kc & 1;
        if (kc + 1 < NCHUNK) { load_stage(kc + 1, s ^ 1); CP_WAIT(1); }
        else { CP_WAIT(0); }
        __syncthreads();

        const uint32_t stage = sbase + s * STAGEB;
#pragma unroll
        for (int ks = 0; ks < 2; ks++) {
            const uint32_t kb = ks * 32;
            uint32_t ah[4][4];
#pragma unroll
            for (int mf = 0; mf < 4; mf++)
                ldsm4(ah[mf], stage + a_off + mf * (16 * TSTRIDE) + kb);
#pragma unroll
            for (int np = 0; np < 4; np++) {
                uint32_t bh[4], bl[4];
                ldsm4(bh, stage + TILEB + b_off + np * (16 * TSTRIDE) + kb);
                ldsm4(bl, stage + 2 * TILEB + b_off + np * (16 * TSTRIDE) + kb);
#pragma unroll
                for (int mf = 0; mf < 4; mf++) {
#pragma unroll
                    for (int half = 0; half < 2; half++) {
                        float* d = acc[mf][np * 2 + half];
                        mma16816(d, ah[mf], bh + half * 2);
                        mma16816(d, ah[mf], bl + half * 2);
                    }
                }
            }
        }
        __syncthreads();
    }

    const int er = lane >> 2;
    const int ec = (lane & 3) * 2;
#pragma unroll
    for (int mf = 0; mf < 4; mf++) {
        size_t row0 = tileM + warp_m + mf * 16 + er;
#pragma unroll
        for (int nf = 0; nf < 8; nf++) {
            size_t col = tileN + warp_n + nf * 8 + ec;
            float f0 = acc[mf][nf][0], f1 = acc[mf][nf][1];
            float f2 = acc[mf][nf][2], f3 = acc[mf][nf][3];
            if (o.Cf) {
                float bx = 0.f, by = 0.f;
                if (o.bias) { bx = o.bias[col]; by = o.bias[col + 1]; }
                float2 v0 = {f0 + bx, f1 + by};
                float2 v1 = {f2 + bx, f3 + by};
                *reinterpret_cast<float2*>(o.Cf + row0 * N + col) = v0;
                *reinterpret_cast<float2*>(o.Cf + (row0 + 8) * N + col) = v1;
            } else {
                *reinterpret_cast<uint32_t*>(o.Ch + row0 * N + col)       = pack2(f0, f1);
                *reinterpret_cast<uint32_t*>(o.Ch + (row0 + 8) * N + col) = pack2(f2, f3);
                if (o.Cl) {
                    *reinterpret_cast<uint32_t*>(o.Cl + row0 * N + col)       = pack2(res_lo(f0), res_lo(f1));
                    *reinterpret_cast<uint32_t*>(o.Cl + (row0 + 8) * N + col) = pack2(res_lo(f2), res_lo(f3));
                }
            }
        }
    }
}

// ---- fused QKV: grid (N/128, M/128, 3); z selects weight/output ----
__global__ void __launch_bounds__(128, 2) qkv_tc()
{
    extern __shared__ char smem[];
    const int z = blockIdx.z;
    GemmOut o;
    o.Cf = nullptr; o.bias = nullptr;
    o.Ch = (z == 0) ? g_Qh : (z == 1) ? g_Kh : g_Vh;
    o.Cl = (z == 0) ? nullptr : (z == 1) ? g_Kl : g_Vl;
    gemm_body(g_Ah, g_Whi[z], g_Wlo[z],
              o, (size_t)blockIdx.y * 128, (size_t)blockIdx.x * 128, smem);
}

// ---- AO projection: fp32 out + bias ----
__global__ void __launch_bounds__(128, 2) o_tc(const float* __restrict__ bias,
                                               float* __restrict__ out)
{
    extern __shared__ char smem[];
    GemmOut o;
    o.Cf = out; o.bias = bias; o.Ch = nullptr; o.Cl = nullptr;
    gemm_body(g_AOh, g_Whi[3], g_Wlo[3],
              o, (size_t)blockIdx.y * 128, (size_t)blockIdx.x * 128, smem);
}

// ============================================================
// Kernel 3: flash attention, 2-pass split fp16 FA2, software
// pipelined: K double-buffered, V load overlapped with QK.
// BQ=128, BK=64, hd=160. 8 warps x 16 rows. grid (16, 8, 2).
// ============================================================
#define AQ_ROWB 336                      // 168 halves per row
#define Q_TILEB (128 * AQ_ROWB)          // 43008
#define K_ARRB (64 * AQ_ROWB)            // 21504 (one of hi/lo)
#define K_STAGEB (2 * K_ARRB)            // 43008 (Kh + Kl)
#define ATTN_SMEM (Q_TILEB + 2 * K_STAGEB + K_STAGEB)   // 172032

__global__ void __launch_bounds__(256) attn_tc()
{
    extern __shared__ char sm[];
    const uint32_t sb = smem_u32(sm);
    const uint32_t Q_s = sb;
    const uint32_t K_s0 = sb + Q_TILEB;            // two stages of (Kh,Kl)
    const uint32_t V_s = sb + Q_TILEB + 2 * K_STAGEB;   // (Vh,Vl)

    const int qt = blockIdx.x, h = blockIdx.y, b = blockIdx.z;
    const int tid = threadIdx.x, lane = tid & 31, wid = tid >> 5;
    const float cscale = rsqrtf((float)HDIM) * 1.44269504f;   // attn_scale * log2(e)

    const size_t qtok = (size_t)b * SEQ + (size_t)qt * 128;
    const size_t hoff = (size_t)h * HDIM;

    auto load_K = [&](int kt, int s) {
        const size_t ktok = (size_t)b * SEQ + (size_t)kt * 64;
        uint32_t dst = K_s0 + (uint32_t)s * K_STAGEB;
#pragma unroll
        for (int i = 0; i < 10; i++) {
            int idx = i * 256 + tid;
            int arr = idx / 1280;
            int rem = idx - arr * 1280;
            int r = rem / 20, c = rem - r * 20;
            cp16(dst + arr * K_ARRB + r * AQ_ROWB + c * 16,
                 (arr ? g_Kl : g_Kh) + (ktok + r) * DD + hoff + c * 8);
        }
    };
    auto load_V = [&](int kt) {
        const size_t ktok = (size_t)b * SEQ + (size_t)kt * 64;
#pragma unroll
        for (int i = 0; i < 10; i++) {
            int idx = i * 256 + tid;
            int arr = idx / 1280;
            int rem = idx - arr * 1280;
            int r = rem / 20, c = rem - r * 20;
            cp16(V_s + arr * K_ARRB + r * AQ_ROWB + c * 16,
                 (arr ? g_Vl : g_Vh) + (ktok + r) * DD + hoff + c * 8);
        }
    };

    // ---- prologue: Q tile + K(0) as group G0 ----
#pragma unroll
    for (int i = 0; i < 10; i++) {
        int idx = i * 256 + tid;
        int r = idx / 20, c = idx - r * 20;
        cp16(Q_s + r * AQ_ROWB + c * 16, g_Qh + (qtok + r) * DD + hoff + c * 8);
    }
    load_K(0, 0);
    CP_COMMIT();

    float m0 = -1e30f, m1 = -1e30f, l0 = 0.f, l1 = 0.f;
    float oacc[20][4];
#pragma unroll
    for (int v = 0; v < 20; v++)
#pragma unroll
        for (int j = 0; j < 4; j++) oacc[v][j] = 0.f;

    const uint32_t qa_off = (uint32_t)((wid * 16 + (lane & 15)) * AQ_ROWB + (lane >> 4) * 16);
    const uint32_t kb_lane = (uint32_t)((((lane >> 4) & 1) * 8 + (lane & 7)) * AQ_ROWB + ((lane >> 3) & 1) * 16);
    const uint32_t v_lane = (uint32_t)((lane & 15) * AQ_ROWB + (lane >> 4) * 16);

    for (int kt = 0; kt < SEQ / 64; kt++) {
        // issue V(kt); prefetch K(kt+1) into other stage
        load_V(kt);
        CP_COMMIT();
        if (kt + 1 < SEQ / 64) load_K(kt + 1, (kt + 1) & 1);
        CP_COMMIT();                     // possibly-empty group keeps counts uniform

        CP_WAIT(2);                      // K(kt) (and Q) resident
        __syncthreads();

        // ---- S = Q K^T : Qh * (Kh + Kl), 2 passes ----
        const uint32_t Kst = K_s0 + (uint32_t)(kt & 1) * K_STAGEB;
        float sacc[8][4];
#pragma unroll
        for (int nt = 0; nt < 8; nt++)
#pragma unroll
            for (int j = 0; j < 4; j++) sacc[nt][j] = 0.f;

#pragma unroll
        for (int k = 0; k < 10; k++) {
            uint32_t ah[4];
            ldsm4(ah, Q_s + qa_off + k * 32);
#pragma unroll
            for (int np = 0; np < 4; np++) {
                uint32_t bh[4], bl[4];
                uint32_t kaddr = Kst + (uint32_t)(np * 16 * AQ_ROWB) + kb_lane + k * 32;
                ldsm4(bh, kaddr);
                ldsm4(bl, kaddr + K_ARRB);
#pragma unroll
                for (int half = 0; half < 2; half++) {
                    float* d = sacc[np * 2 + half];
                    mma16816(d, ah, bh + half * 2);
                    mma16816(d, ah, bl + half * 2);
                }
            }
        }

        // ---- online softmax ----
        float mx0 = -1e30f, mx1 = -1e30f;
#pragma unroll
        for (int nt = 0; nt < 8; nt++) {
            sacc[nt][0] *= cscale; sacc[nt][1] *= cscale;
            sacc[nt][2] *= cscale; sacc[nt][3] *= cscale;
            mx0 = fmaxf(mx0, fmaxf(sacc[nt][0], sacc[nt][1]));
            mx1 = fmaxf(mx1, fmaxf(sacc[nt][2], sacc[nt][3]));
        }
        mx0 = fmaxf(mx0, __shfl_xor_sync(0xffffffffu, mx0, 1));
        mx0 = fmaxf(mx0, __shfl_xor_sync(0xffffffffu, mx0, 2));
        mx1 = fmaxf(mx1, __shfl_xor_sync(0xffffffffu, mx1, 1));
        mx1 = fmaxf(mx1, __shfl_xor_sync(0xffffffffu, mx1, 2));
        float nm0 = fmaxf(m0, mx0), nm1 = fmaxf(m1, mx1);
        float al0 = ex2f(m0 - nm0), al1 = ex2f(m1 - nm1);
        m0 = nm0; m1 = nm1;

        float ps0 = 0.f, ps1 = 0.f;
#pragma unroll
        for (int nt = 0; nt < 8; nt++) {
            sacc[nt][0] = ex2f(sacc[nt][0] - nm0);
            sacc[nt][1] = ex2f(sacc[nt][1] - nm0);
            sacc[nt][2] = ex2f(sacc[nt][2] - nm1);
            sacc[nt][3] = ex2f(sacc[nt][3] - nm1);
            ps0 += sacc[nt][0] + sacc[nt][1];
            ps1 += sacc[nt][2] + sacc[nt][3];
        }
        ps0 += __shfl_xor_sync(0xffffffffu, ps0, 1);
        ps0 += __shfl_xor_sync(0xffffffffu, ps0, 2);
        ps1 += __shfl_xor_sync(0xffffffffu, ps1, 1);
        ps1 += __shfl_xor_sync(0xffffffffu, ps1, 2);
        l0 = l0 * al0 + ps0;
        l1 = l1 * al1 + ps1;

#pragma unroll
        for (int v = 0; v < 20; v++) {
            oacc[v][0] *= al0; oacc[v][1] *= al0;
            oacc[v][2] *= al1; oacc[v][3] *= al1;
        }

        CP_WAIT(1);                      // V(kt) resident (K(kt+1) may still fly)
        __syncthreads();

        // ---- O += P V : Ph * (Vh + Vl), 2 passes ----
#pragma unroll
        for (int kt2 = 0; kt2 < 4; kt2++) {
            const float* p0 = sacc[2 * kt2];
            const float* p1 = sacc[2 * kt2 + 1];
            uint32_t pah[4];
            pah[0] = pack2(p0[0], p0[1]);
            pah[1] = pack2(p0[2], p0[3]);
            pah[2] = pack2(p1[0], p1[1]);
            pah[3] = pack2(p1[2], p1[3]);
#pragma unroll
            for (int vp = 0; vp < 10; vp++) {
                uint32_t bvh[4], bvl[4];
                uint32_t vaddr = V_s + (uint32_t)(kt2 * 16 * AQ_ROWB) + v_lane + vp * 32;
                ldsm4t(bvh, vaddr);
                ldsm4t(bvl, vaddr + K_ARRB);
#pragma unroll
                for (int half = 0; half < 2; half++) {
                    float* d = oacc[vp * 2 + half];
                    mma16816(d, pah, bvh + half * 2);
                    mma16816(d, pah, bvl + half * 2);
                }
            }
        }
        __syncthreads();                 // PV reads done before next V overwrite
    }

    // ---- epilogue: normalize, store fp16 hi (A-side of o-proj) ----
    float inv0 = 1.f / l0, inv1 = 1.f / l1;
    const size_t tok0 = qtok + wid * 16 + (lane >> 2);
    const size_t tok1 = tok0 + 8;
#pragma unroll
    for (int nt = 0; nt < 20; nt++) {
        size_t col = hoff + nt * 8 + (lane & 3) * 2;
        *reinterpret_cast<uint32_t*>(g_AOh + tok0 * DD + col) = pack2(oacc[nt][0] * inv0, oacc[nt][1] * inv0);
        *reinterpret_cast<uint32_t*>(g_AOh + tok1 * DD + col) = pack2(oacc[nt][2] * inv1, oacc[nt][3] * inv1);
    }
}

// ============================================================
// host launcher
// ============================================================
extern "C" void kernel_launch(void* const* d_in, const int* in_sizes, int n_in,
                              void* d_out, int out_size)
{
    const float* x   = (const float*)d_in[0];
    const float* pal = (const float*)d_in[1];
    const float* Wq  = (const float*)d_in[2];
    const float* Wk  = (const float*)d_in[3];
    const float* Wv  = (const float*)d_in[4];
    const float* Wo  = (const float*)d_in[5];
    const float* bo  = (const float*)d_in[6];
    const float* qd  = (const float*)d_in[7];
    const float* qu  = (const float*)d_in[8];
    const float* kd  = (const float*)d_in[9];
    const float* ku  = (const float*)d_in[10];
    const float* vd  = (const float*)d_in[11];
    const float* vu  = (const float*)d_in[12];
    const float* od  = (const float*)d_in[13];
    const float* ou  = (const float*)d_in[14];
    float* out = (float*)d_out;

    cudaFuncSetAttribute(qkv_tc, cudaFuncAttributeMaxDynamicSharedMemorySize, GEMM_SMEM);
    cudaFuncSetAttribute(o_tc, cudaFuncAttributeMaxDynamicSharedMemorySize, GEMM_SMEM);
    cudaFuncSetAttribute(attn_tc, cudaFuncAttributeMaxDynamicSharedMemorySize, ATTN_SMEM);

    // 0) palette contractions
    k_downup<<<(8 * RK * DD + 255) / 256, 256>>>(pal, qd, qu, kd, ku, vd, vu, od, ou);
    // 1) effective weights (LoRA folded) -> fp16 hi/lo
    k_weff<<<(4 * DD * DD / 4 + 255) / 256, 256>>>(Wq, Wk, Wv, Wo);
    // 1b) x -> fp16 hi
    k_cvtA<<<(NTOK * DD / 4 + 255) / 256, 256>>>(x);
    // 2) fused Q,K,V projections (one launch, 960 CTAs of 128 thr)
    dim3 gqkv(DD / 128, NTOK / 128, 3);
    qkv_tc<<<gqkv, 128, GEMM_SMEM>>>();
    // 3) attention (pipelined) -> fp16 hi AO
    dim3 gattn(SEQ / 128, NH, NB);
    attn_tc<<<gattn, 256, ATTN_SMEM>>>();
    // 4) output projection + bias -> fp32 out
    dim3 go(DD / 128, NTOK / 128);
    o_tc<<<go, 128, GEMM_SMEM>>>(bo, out);
}

// round 16
// speedup vs baseline: 1.0967x; 1.0967x over previous
#include <cuda_runtime.h>
#include <cuda_fp16.h>
#include <math.h>
#include <cstdint>

#define DD 1280
#define NH 8
#define HDIM 160
#define RK 4
#define NB 2
#define SEQ 2048
#define NTOK (NB*SEQ)

// ---- scratch (static __device__ arrays; no allocation) ----
__device__ float g_down[4][RK*DD];
__device__ float g_up[4][RK*DD];
__device__ __half g_Whi[4][DD*DD];
__device__ __half g_Wlo[4][DD*DD];
__device__ __half g_Ah[NTOK*DD];        // x, fp16 hi only
__device__ __half g_Qh[NTOK*DD];
__device__ __half g_Kh[NTOK*DD];
__device__ __half g_Kl[NTOK*DD];
__device__ __half g_Vh[NTOK*DD];
__device__ __half g_Vl[NTOK*DD];
__device__ __half g_AOh[NTOK*DD];

// ============================================================
// helpers (family-portable, sm_80+)
// ============================================================
__device__ __forceinline__ uint32_t smem_u32(const void* p) {
    uint32_t a;
    asm("{ .reg .u64 t; cvta.to.shared.u64 t, %1; cvt.u32.u64 %0, t; }" : "=r"(a) : "l"(p));
    return a;
}
__device__ __forceinline__ void cp16(uint32_t dst, const void* src) {
    asm volatile("cp.async.cg.shared.global [%0], [%1], 16;" :: "r"(dst), "l"(src) : "memory");
}
#define CP_COMMIT() asm volatile("cp.async.commit_group;" ::: "memory")
#define CP_WAIT(n)  asm volatile("cp.async.wait_group %0;" :: "n"(n) : "memory")

__device__ __forceinline__ void ldsm4(uint32_t* r, uint32_t addr) {
    asm volatile("ldmatrix.sync.aligned.m8n8.x4.shared.b16 {%0,%1,%2,%3}, [%4];"
        : "=r"(r[0]), "=r"(r[1]), "=r"(r[2]), "=r"(r[3]) : "r"(addr));
}
__device__ __forceinline__ void ldsm4t(uint32_t* r, uint32_t addr) {
    asm volatile("ldmatrix.sync.aligned.m8n8.x4.trans.shared.b16 {%0,%1,%2,%3}, [%4];"
        : "=r"(r[0]), "=r"(r[1]), "=r"(r[2]), "=r"(r[3]) : "r"(addr));
}
__device__ __forceinline__ void mma16816(float* d, const uint32_t* a, const uint32_t* b) {
    asm volatile(
        "mma.sync.aligned.m16n8k16.row.col.f32.f16.f16.f32 "
        "{%0,%1,%2,%3}, {%4,%5,%6,%7}, {%8,%9}, {%0,%1,%2,%3};"
        : "+f"(d[0]), "+f"(d[1]), "+f"(d[2]), "+f"(d[3])
        : "r"(a[0]), "r"(a[1]), "r"(a[2]), "r"(a[3]), "r"(b[0]), "r"(b[1]));
}
__device__ __forceinline__ float ex2f(float x) {
    float y; asm("ex2.approx.f32 %0, %1;" : "=f"(y) : "f"(x)); return y;
}
__device__ __forceinline__ uint32_t pack2(float a, float b) {
    __half2 v = __floats2half2_rn(a, b);
    return reinterpret_cast<uint32_t&>(v);
}
__device__ __forceinline__ float res_lo(float f) {
    return f - __half2float(__float2half_rn(f));
}

// ============================================================
// Kernel 0: contract palette into down/up vectors for 4 LoRAs
// ============================================================
__global__ void k_downup(const float* __restrict__ pal,
    const float* __restrict__ qd, const float* __restrict__ qu,
    const float* __restrict__ kd, const float* __restrict__ ku,
    const float* __restrict__ vd, const float* __restrict__ vu,
    const float* __restrict__ od, const float* __restrict__ ou)
{
    __shared__ float p[15];
    if (threadIdx.x < 15) p[threadIdx.x] = pal[threadIdx.x];
    __syncthreads();
    int idx = blockIdx.x * blockDim.x + threadIdx.x;
    if (idx >= 8 * RK * DD) return;
    int which = idx / (RK * DD);
    int e = idx - which * (RK * DD);
    const float* srcs[8] = {qd, qu, kd, ku, vd, vu, od, ou};
    const float* s = srcs[which];
    float acc = 0.f;
#pragma unroll
    for (int j = 0; j < 15; j++) acc += p[j] * s[e * 15 + j];
    if (which & 1) g_up[which >> 1][e] = acc;
    else          g_down[which >> 1][e] = acc;
}

// ============================================================
// Kernel 1: W_eff = W + up @ down, written as fp16 hi/lo pair
// ============================================================
__global__ void k_weff(const float* __restrict__ Wq, const float* __restrict__ Wk,
                       const float* __restrict__ Wv, const float* __restrict__ Wo)
{
    const int per_w = DD * DD / 4;
    int idx = blockIdx.x * blockDim.x + threadIdx.x;
    if (idx >= 4 * per_w) return;
    int w = idx / per_w;
    int e4 = idx - w * per_w;
    int o = e4 / (DD / 4);
    int i4 = e4 - o * (DD / 4);
    const float* Ws[4] = {Wq, Wk, Wv, Wo};
    float4 acc = reinterpret_cast<const float4*>(Ws[w])[e4];
#pragma unroll
    for (int r = 0; r < RK; r++) {
        float u = g_up[w][o * RK + r];
        float4 d = reinterpret_cast<const float4*>(&g_down[w][r * DD])[i4];
        acc.x += u * d.x; acc.y += u * d.y; acc.z += u * d.z; acc.w += u * d.w;
    }
    float v[4] = {acc.x, acc.y, acc.z, acc.w};
    reinterpret_cast<uint32_t*>(&g_Whi[w][0])[2*e4]   = pack2(v[0], v[1]);
    reinterpret_cast<uint32_t*>(&g_Whi[w][0])[2*e4+1] = pack2(v[2], v[3]);
    reinterpret_cast<uint32_t*>(&g_Wlo[w][0])[2*e4]   = pack2(res_lo(v[0]), res_lo(v[1]));
    reinterpret_cast<uint32_t*>(&g_Wlo[w][0])[2*e4+1] = pack2(res_lo(v[2]), res_lo(v[3]));
}

// ============================================================
// Kernel 1b: fp32 activation -> fp16 hi only
// ============================================================
__global__ void k_cvtA(const float* __restrict__ src)
{
    int i = blockIdx.x * blockDim.x + threadIdx.x;
    if (i >= NTOK * DD / 4) return;
    float4 a = reinterpret_cast<const float4*>(src)[i];
    reinterpret_cast<uint32_t*>(g_Ah)[2*i]   = pack2(a.x, a.y);
    reinterpret_cast<uint32_t*>(g_Ah)[2*i+1] = pack2(a.z, a.w);
}

// ============================================================
// GEMM core: 128x128 CTA tile, BK=32, 8 warps x (32x64 warp
// tile), 256 threads. 2-pass split fp16: C = Ah @ (Wh+Wl)^T.
// 3-stage cp.async pipeline, 1 sync/chunk, hi/lo MMA sweeps
// separated (same-accumulator distance 4, per-acc order kept).
// ============================================================
#define BK 32
#define TSTRIDE 80
#define TILEB (128 * TSTRIDE)
#define STAGEB (3 * TILEB)         // Ah, Wh, Wl
#define GEMM_SMEM (3 * STAGEB)     // 3 pipeline stages = 92160
#define NCHUNK (DD / BK)

struct GemmOut {
    float* Cf; const float* bias;
    __half* Ch; __half* Cl;        // Cl may be null (hi-only output)
};

__device__ __forceinline__ void gemm_body(
    const __half* __restrict__ Ah, const __half* __restrict__ Whi,
    const __half* __restrict__ Wlo,
    const GemmOut& o, size_t tileM, size_t tileN, char* smem)
{
    const uint32_t sbase = smem_u32(smem);
    const int tid = threadIdx.x;
    const int lane = tid & 31, wid = tid >> 5;        // 8 warps
    const int warp_m = (wid & 3) * 32, warp_n = (wid >> 2) * 64;
    const int K = DD, N = DD;

    const __half* srcs[3] = {Ah, Whi, Wlo};

    auto load_stage = [&](int kc, int s) {
        const int kcol = kc * BK;
        uint32_t dst0 = sbase + s * STAGEB;
#pragma unroll
        for (int i = 0; i < 6; i++) {
            int idx = i * 256 + tid;           // 3 tiles x 128 rows x 4 chunks
            int t = idx >> 9;
            int rem = idx & 511;
            int r = rem >> 2, c = rem & 3;
            size_t grow = (t == 0) ? (tileM + r) : (tileN + r);
            const __half* src = srcs[t] + grow * K + kcol + c * 8;
            cp16(dst0 + t * TILEB + r * TSTRIDE + c * 16, src);
        }
        CP_COMMIT();
    };

    float acc[2][8][4];
#pragma unroll
    for (int mf = 0; mf < 2; mf++)
#pragma unroll
        for (int nf = 0; nf < 8; nf++)
#pragma unroll
            for (int j = 0; j < 4; j++) acc[mf][nf][j] = 0.f;

    load_stage(0, 0);
    load_stage(1, 1);

    const int a_row = warp_m + ((lane >> 3) & 1) * 8 + (lane & 7);
    const uint32_t a_off = (uint32_t)(a_row * TSTRIDE + (lane >> 4) * 16);
    const int b_row = warp_n + ((lane >> 4) & 1) * 8 + (lane & 7);
    const uint32_t b_off = (uint32_t)(b_row * TSTRIDE + ((lane >> 3) & 1) * 16);

    for (int kc = 0; kc < NCHUNK; kc++) {
        CP_WAIT(1);                 // group kc done; kc+1 may still fly
        __syncthreads();            // data visible to all; all warps done kc-1

        const uint32_t stage = sbase + (uint32_t)(kc % 3) * STAGEB;
#pragma unroll
        for (int ks = 0; ks < 2; ks++) {
            const uint32_t kb = ks * 32;
            uint32_t ah[2][4];
#pragma unroll
            for (int mf = 0; mf < 2; mf++)
                ldsm4(ah[mf], stage + a_off + mf * (16 * TSTRIDE) + kb);
#pragma unroll
            for (int np = 0; np < 4; np++) {
                uint32_t bh[4], bl[4];
                ldsm4(bh, stage + TILEB + b_off + np * (16 * TSTRIDE) + kb);
                ldsm4(bl, stage + 2 * TILEB + b_off + np * (16 * TSTRIDE) + kb);
                // hi sweep (4 independent accs), then lo sweep: per-acc
                // order (hi before lo) preserved -> bit-identical
#pragma unroll
                for (int mf = 0; mf < 2; mf++)
#pragma unroll
                    for (int half = 0; half < 2; half++)
                        mma16816(acc[mf][np * 2 + half], ah[mf], bh + half * 2);
#pragma unroll
                for (int mf = 0; mf < 2; mf++)
#pragma unroll
                    for (int half = 0; half < 2; half++)
                        mma16816(acc[mf][np * 2 + half], ah[mf], bl + half * 2);
            }
        }
        // prefetch kc+2 into buffer (kc+2)%3 == (kc-1)%3: every warp has
        // passed this iteration's barrier, so all finished compute(kc-1).
        if (kc + 2 < NCHUNK) load_stage(kc + 2, (kc + 2) % 3);
    }

    const int er = lane >> 2;
    const int ec = (lane & 3) * 2;
#pragma unroll
    for (int mf = 0; mf < 2; mf++) {
        size_t row0 = tileM + warp_m + mf * 16 + er;
#pragma unroll
        for (int nf = 0; nf < 8; nf++) {
            size_t col = tileN + warp_n + nf * 8 + ec;
            float f0 = acc[mf][nf][0], f1 = acc[mf][nf][1];
            float f2 = acc[mf][nf][2], f3 = acc[mf][nf][3];
            if (o.Cf) {
                float bx = 0.f, by = 0.f;
                if (o.bias) { bx = o.bias[col]; by = o.bias[col + 1]; }
                float2 v0 = {f0 + bx, f1 + by};
                float2 v1 = {f2 + bx, f3 + by};
                *reinterpret_cast<float2*>(o.Cf + row0 * N + col) = v0;
                *reinterpret_cast<float2*>(o.Cf + (row0 + 8) * N + col) = v1;
            } else {
                *reinterpret_cast<uint32_t*>(o.Ch + row0 * N + col)       = pack2(f0, f1);
                *reinterpret_cast<uint32_t*>(o.Ch + (row0 + 8) * N + col) = pack2(f2, f3);
                if (o.Cl) {
                    *reinterpret_cast<uint32_t*>(o.Cl + row0 * N + col)       = pack2(res_lo(f0), res_lo(f1));
                    *reinterpret_cast<uint32_t*>(o.Cl + (row0 + 8) * N + col) = pack2(res_lo(f2), res_lo(f3));
                }
            }
        }
    }
}

// ---- fused QKV: grid (N/128, M/128, 3); z selects weight/output ----
__global__ void __launch_bounds__(256, 2) qkv_tc()
{
    extern __shared__ char smem[];
    const int z = blockIdx.z;
    GemmOut o;
    o.Cf = nullptr; o.bias = nullptr;
    o.Ch = (z == 0) ? g_Qh : (z == 1) ? g_Kh : g_Vh;
    o.Cl = (z == 0) ? nullptr : (z == 1) ? g_Kl : g_Vl;
    gemm_body(g_Ah, g_Whi[z], g_Wlo[z],
              o, (size_t)blockIdx.y * 128, (size_t)blockIdx.x * 128, smem);
}

// ---- AO projection: fp32 out + bias ----
__global__ void __launch_bounds__(256, 2) o_tc(const float* __restrict__ bias,
                                               float* __restrict__ out)
{
    extern __shared__ char smem[];
    GemmOut o;
    o.Cf = out; o.bias = bias; o.Ch = nullptr; o.Cl = nullptr;
    gemm_body(g_AOh, g_Whi[3], g_Wlo[3],
              o, (size_t)blockIdx.y * 128, (size_t)blockIdx.x * 128, smem);
}

// ============================================================
// Kernel 3: flash attention, 2-pass split fp16 FA2, software
// pipelined: K double-buffered, V load overlapped with QK.
// BQ=128, BK=64, hd=160. 8 warps x 16 rows. grid (16, 8, 2).
// QK: all K fragments preloaded, hi sweep then lo sweep.
// ============================================================
#define AQ_ROWB 336                      // 168 halves per row
#define Q_TILEB (128 * AQ_ROWB)          // 43008
#define K_ARRB (64 * AQ_ROWB)            // 21504 (one of hi/lo)
#define K_STAGEB (2 * K_ARRB)            // 43008 (Kh + Kl)
#define ATTN_SMEM (Q_TILEB + 2 * K_STAGEB + K_STAGEB)   // 172032

__global__ void __launch_bounds__(256) attn_tc()
{
    extern __shared__ char sm[];
    const uint32_t sb = smem_u32(sm);
    const uint32_t Q_s = sb;
    const uint32_t K_s0 = sb + Q_TILEB;            // two stages of (Kh,Kl)
    const uint32_t V_s = sb + Q_TILEB + 2 * K_STAGEB;   // (Vh,Vl)

    const int qt = blockIdx.x, h = blockIdx.y, b = blockIdx.z;
    const int tid = threadIdx.x, lane = tid & 31, wid = tid >> 5;
    const float cscale = rsqrtf((float)HDIM) * 1.44269504f;   // attn_scale * log2(e)

    const size_t qtok = (size_t)b * SEQ + (size_t)qt * 128;
    const size_t hoff = (size_t)h * HDIM;

    auto load_K = [&](int kt, int s) {
        const size_t ktok = (size_t)b * SEQ + (size_t)kt * 64;
        uint32_t dst = K_s0 + (uint32_t)s * K_STAGEB;
#pragma unroll
        for (int i = 0; i < 10; i++) {
            int idx = i * 256 + tid;
            int arr = idx / 1280;
            int rem = idx - arr * 1280;
            int r = rem / 20, c = rem - r * 20;
            cp16(dst + arr * K_ARRB + r * AQ_ROWB + c * 16,
                 (arr ? g_Kl : g_Kh) + (ktok + r) * DD + hoff + c * 8);
        }
    };
    auto load_V = [&](int kt) {
        const size_t ktok = (size_t)b * SEQ + (size_t)kt * 64;
#pragma unroll
        for (int i = 0; i < 10; i++) {
            int idx = i * 256 + tid;
            int arr = idx / 1280;
            int rem = idx - arr * 1280;
            int r = rem / 20, c = rem - r * 20;
            cp16(V_s + arr * K_ARRB + r * AQ_ROWB + c * 16,
                 (arr ? g_Vl : g_Vh) + (ktok + r) * DD + hoff + c * 8);
        }
    };

    // ---- prologue: Q tile + K(0) as group G0 ----
#pragma unroll
    for (int i = 0; i < 10; i++) {
        int idx = i * 256 + tid;
        int r = idx / 20, c = idx - r * 20;
        cp16(Q_s + r * AQ_ROWB + c * 16, g_Qh + (qtok + r) * DD + hoff + c * 8);
    }
    load_K(0, 0);
    CP_COMMIT();

    float m0 = -1e30f, m1 = -1e30f, l0 = 0.f, l1 = 0.f;
    float oacc[20][4];
#pragma unroll
    for (int v = 0; v < 20; v++)
#pragma unroll
        for (int j = 0; j < 4; j++) oacc[v][j] = 0.f;

    const uint32_t qa_off = (uint32_t)((wid * 16 + (lane & 15)) * AQ_ROWB + (lane >> 4) * 16);
    const uint32_t kb_lane = (uint32_t)((((lane >> 4) & 1) * 8 + (lane & 7)) * AQ_ROWB + ((lane >> 3) & 1) * 16);
    const uint32_t v_lane = (uint32_t)((lane & 15) * AQ_ROWB + (lane >> 4) * 16);

    for (int kt = 0; kt < SEQ / 64; kt++) {
        // issue V(kt); prefetch K(kt+1) into other stage
        load_V(kt);
        CP_COMMIT();
        if (kt + 1 < SEQ / 64) load_K(kt + 1, (kt + 1) & 1);
        CP_COMMIT();                     // possibly-empty group keeps counts uniform

        CP_WAIT(2);                      // K(kt) (and Q) resident
        __syncthreads();

        // ---- S = Q K^T : Qh * (Kh + Kl), hi sweep then lo sweep ----
        const uint32_t Kst = K_s0 + (uint32_t)(kt & 1) * K_STAGEB;
        float sacc[8][4];
#pragma unroll
        for (int nt = 0; nt < 8; nt++)
#pragma unroll
            for (int j = 0; j < 4; j++) sacc[nt][j] = 0.f;

#pragma unroll
        for (int k = 0; k < 10; k++) {
            uint32_t ah[4];
            ldsm4(ah, Q_s + qa_off + k * 32);
            uint32_t bh[4][4], bl[4][4];
#pragma unroll
            for (int np = 0; np < 4; np++) {
                uint32_t kaddr = Kst + (uint32_t)(np * 16 * AQ_ROWB) + kb_lane + k * 32;
                ldsm4(bh[np], kaddr);
                ldsm4(bl[np], kaddr + K_ARRB);
            }
#pragma unroll
            for (int np = 0; np < 4; np++)
#pragma unroll
                for (int half = 0; half < 2; half++)
                    mma16816(sacc[np * 2 + half], ah, bh[np] + half * 2);
#pragma unroll
            for (int np = 0; np < 4; np++)
#pragma unroll
                for (int half = 0; half < 2; half++)
                    mma16816(sacc[np * 2 + half], ah, bl[np] + half * 2);
        }

        // ---- online softmax ----
        float mx0 = -1e30f, mx1 = -1e30f;
#pragma unroll
        for (int nt = 0; nt < 8; nt++) {
            sacc[nt][0] *= cscale; sacc[nt][1] *= cscale;
            sacc[nt][2] *= cscale; sacc[nt][3] *= cscale;
            mx0 = fmaxf(mx0, fmaxf(sacc[nt][0], sacc[nt][1]));
            mx1 = fmaxf(mx1, fmaxf(sacc[nt][2], sacc[nt][3]));
        }
        mx0 = fmaxf(mx0, __shfl_xor_sync(0xffffffffu, mx0, 1));
        mx0 = fmaxf(mx0, __shfl_xor_sync(0xffffffffu, mx0, 2));
        mx1 = fmaxf(mx1, __shfl_xor_sync(0xffffffffu, mx1, 1));
        mx1 = fmaxf(mx1, __shfl_xor_sync(0xffffffffu, mx1, 2));
        float nm0 = fmaxf(m0, mx0), nm1 = fmaxf(m1, mx1);
        float al0 = ex2f(m0 - nm0), al1 = ex2f(m1 - nm1);
        m0 = nm0; m1 = nm1;

        float ps0 = 0.f, ps1 = 0.f;
#pragma unroll
        for (int nt = 0; nt < 8; nt++) {
            sacc[nt][0] = ex2f(sacc[nt][0] - nm0);
            sacc[nt][1] = ex2f(sacc[nt][1] - nm0);
            sacc[nt][2] = ex2f(sacc[nt][2] - nm1);
            sacc[nt][3] = ex2f(sacc[nt][3] - nm1);
            ps0 += sacc[nt][0] + sacc[nt][1];
            ps1 += sacc[nt][2] + sacc[nt][3];
        }
        ps0 += __shfl_xor_sync(0xffffffffu, ps0, 1);
        ps0 += __shfl_xor_sync(0xffffffffu, ps0, 2);
        ps1 += __shfl_xor_sync(0xffffffffu, ps1, 1);
        ps1 += __shfl_xor_sync(0xffffffffu, ps1, 2);
        l0 = l0 * al0 + ps0;
        l1 = l1 * al1 + ps1;

#pragma unroll
        for (int v = 0; v < 20; v++) {
            oacc[v][0] *= al0; oacc[v][1] *= al0;
            oacc[v][2] *= al1; oacc[v][3] *= al1;
        }

        CP_WAIT(1);                      // V(kt) resident (K(kt+1) may still fly)
        __syncthreads();

        // ---- O += P V : Ph * (Vh + Vl), hi pair then lo pair ----
#pragma unroll
        for (int kt2 = 0; kt2 < 4; kt2++) {
            const float* p0 = sacc[2 * kt2];
            const float* p1 = sacc[2 * kt2 + 1];
            uint32_t pah[4];
            pah[0] = pack2(p0[0], p0[1]);
            pah[1] = pack2(p0[2], p0[3]);
            pah[2] = pack2(p1[0], p1[1]);
            pah[3] = pack2(p1[2], p1[3]);
#pragma unroll
            for (int vp = 0; vp < 10; vp++) {
                uint32_t bvh[4], bvl[4];
                uint32_t vaddr = V_s + (uint32_t)(kt2 * 16 * AQ_ROWB) + v_lane + vp * 32;
                ldsm4t(bvh, vaddr);
                ldsm4t(bvl, vaddr + K_ARRB);
                mma16816(oacc[vp * 2 + 0], pah, bvh + 0);
                mma16816(oacc[vp * 2 + 1], pah, bvh + 2);
                mma16816(oacc[vp * 2 + 0], pah, bvl + 0);
                mma16816(oacc[vp * 2 + 1], pah, bvl + 2);
            }
        }
        __syncthreads();                 // PV reads done before next V overwrite
    }

    // ---- epilogue: normalize, store fp16 hi (A-side of o-proj) ----
    float inv0 = 1.f / l0, inv1 = 1.f / l1;
    const size_t tok0 = qtok + wid * 16 + (lane >> 2);
    const size_t tok1 = tok0 + 8;
#pragma unroll
    for (int nt = 0; nt < 20; nt++) {
        size_t col = hoff + nt * 8 + (lane & 3) * 2;
        *reinterpret_cast<uint32_t*>(g_AOh + tok0 * DD + col) = pack2(oacc[nt][0] * inv0, oacc[nt][1] * inv0);
        *reinterpret_cast<uint32_t*>(g_AOh + tok1 * DD + col) = pack2(oacc[nt][2] * inv1, oacc[nt][3] * inv1);
    }
}

// ============================================================
// host launcher
// ============================================================
extern "C" void kernel_launch(void* const* d_in, const int* in_sizes, int n_in,
                              void* d_out, int out_size)
{
    const float* x   = (const float*)d_in[0];
    const float* pal = (const float*)d_in[1];
    const float* Wq  = (const float*)d_in[2];
    const float* Wk  = (const float*)d_in[3];
    const float* Wv  = (const float*)d_in[4];
    const float* Wo  = (const float*)d_in[5];
    const float* bo  = (const float*)d_in[6];
    const float* qd  = (const float*)d_in[7];
    const float* qu  = (const float*)d_in[8];
    const float* kd  = (const float*)d_in[9];
    const float* ku  = (const float*)d_in[10];
    const float* vd  = (const float*)d_in[11];
    const float* vu  = (const float*)d_in[12];
    const float* od  = (const float*)d_in[13];
    const float* ou  = (const float*)d_in[14];
    float* out = (float*)d_out;

    cudaFuncSetAttribute(qkv_tc, cudaFuncAttributeMaxDynamicSharedMemorySize, GEMM_SMEM);
    cudaFuncSetAttribute(o_tc, cudaFuncAttributeMaxDynamicSharedMemorySize, GEMM_SMEM);
    cudaFuncSetAttribute(attn_tc, cudaFuncAttributeMaxDynamicSharedMemorySize, ATTN_SMEM);

    // 0) palette contractions
    k_downup<<<(8 * RK * DD + 255) / 256, 256>>>(pal, qd, qu, kd, ku, vd, vu, od, ou);
    // 1) effective weights (LoRA folded) -> fp16 hi/lo
    k_weff<<<(4 * DD * DD / 4 + 255) / 256, 256>>>(Wq, Wk, Wv, Wo);
    // 1b) x -> fp16 hi
    k_cvtA<<<(NTOK * DD / 4 + 255) / 256, 256>>>(x);
    // 2) fused Q,K,V projections (one launch, 960 CTAs of 256 thr)
    dim3 gqkv(DD / 128, NTOK / 128, 3);
    qkv_tc<<<gqkv, 256, GEMM_SMEM>>>();
    // 3) attention (pipelined) -> fp16 hi AO
    dim3 gattn(SEQ / 128, NH, NB);
    attn_tc<<<gattn, 256, ATTN_SMEM>>>();
    // 4) output projection + bias -> fp32 out
    dim3 go(DD / 128, NTOK / 128);
    o_tc<<<go, 256, GEMM_SMEM>>>(bo, out);
}

// round 17
// speedup vs baseline: 1.1021x; 1.0049x over previous
#include <cuda_runtime.h>
#include <cuda_fp16.h>
#include <math.h>
#include <cstdint>

#define DD 1280
#define NH 8
#define HDIM 160
#define RK 4
#define NB 2
#define SEQ 2048
#define NTOK (NB*SEQ)

// ---- scratch (static __device__ arrays; no allocation) ----
__device__ float g_down[4][RK*DD];
__device__ float g_up[4][RK*DD];
__device__ __half g_Whi[4][DD*DD];
__device__ __half g_Wlo[4][DD*DD];
__device__ __half g_Ah[NTOK*DD];        // x, fp16 hi only
__device__ __half g_Qh[NTOK*DD];
__device__ __half g_Kh[NTOK*DD];
__device__ __half g_Kl[NTOK*DD];
__device__ __half g_Vh[NTOK*DD];
__device__ __half g_Vl[NTOK*DD];
__device__ __half g_AOh[NTOK*DD];

// ============================================================
// helpers (family-portable, sm_80+)
// ============================================================
__device__ __forceinline__ uint32_t smem_u32(const void* p) {
    uint32_t a;
    asm("{ .reg .u64 t; cvta.to.shared.u64 t, %1; cvt.u32.u64 %0, t; }" : "=r"(a) : "l"(p));
    return a;
}
__device__ __forceinline__ void cp16(uint32_t dst, const void* src) {
    asm volatile("cp.async.cg.shared.global [%0], [%1], 16;" :: "r"(dst), "l"(src) : "memory");
}
#define CP_COMMIT() asm volatile("cp.async.commit_group;" ::: "memory")
#define CP_WAIT(n)  asm volatile("cp.async.wait_group %0;" :: "n"(n) : "memory")

__device__ __forceinline__ void ldsm4(uint32_t* r, uint32_t addr) {
    asm volatile("ldmatrix.sync.aligned.m8n8.x4.shared.b16 {%0,%1,%2,%3}, [%4];"
        : "=r"(r[0]), "=r"(r[1]), "=r"(r[2]), "=r"(r[3]) : "r"(addr));
}
__device__ __forceinline__ void ldsm4t(uint32_t* r, uint32_t addr) {
    asm volatile("ldmatrix.sync.aligned.m8n8.x4.trans.shared.b16 {%0,%1,%2,%3}, [%4];"
        : "=r"(r[0]), "=r"(r[1]), "=r"(r[2]), "=r"(r[3]) : "r"(addr));
}
__device__ __forceinline__ void mma16816(float* d, const uint32_t* a, const uint32_t* b) {
    asm volatile(
        "mma.sync.aligned.m16n8k16.row.col.f32.f16.f16.f32 "
        "{%0,%1,%2,%3}, {%4,%5,%6,%7}, {%8,%9}, {%0,%1,%2,%3};"
        : "+f"(d[0]), "+f"(d[1]), "+f"(d[2]), "+f"(d[3])
        : "r"(a[0]), "r"(a[1]), "r"(a[2]), "r"(a[3]), "r"(b[0]), "r"(b[1]));
}
__device__ __forceinline__ float ex2f(float x) {
    float y; asm("ex2.approx.f32 %0, %1;" : "=f"(y) : "f"(x)); return y;
}
__device__ __forceinline__ uint32_t pack2(float a, float b) {
    __half2 v = __floats2half2_rn(a, b);
    return reinterpret_cast<uint32_t&>(v);
}
__device__ __forceinline__ float res_lo(float f) {
    return f - __half2float(__float2half_rn(f));
}

// ============================================================
// Kernel 0: contract palette into down/up vectors for 4 LoRAs
// ============================================================
__global__ void k_downup(const float* __restrict__ pal,
    const float* __restrict__ qd, const float* __restrict__ qu,
    const float* __restrict__ kd, const float* __restrict__ ku,
    const float* __restrict__ vd, const float* __restrict__ vu,
    const float* __restrict__ od, const float* __restrict__ ou)
{
    __shared__ float p[15];
    if (threadIdx.x < 15) p[threadIdx.x] = pal[threadIdx.x];
    __syncthreads();
    int idx = blockIdx.x * blockDim.x + threadIdx.x;
    if (idx >= 8 * RK * DD) return;
    int which = idx / (RK * DD);
    int e = idx - which * (RK * DD);
    const float* srcs[8] = {qd, qu, kd, ku, vd, vu, od, ou};
    const float* s = srcs[which];
    float acc = 0.f;
#pragma unroll
    for (int j = 0; j < 15; j++) acc += p[j] * s[e * 15 + j];
    if (which & 1) g_up[which >> 1][e] = acc;
    else          g_down[which >> 1][e] = acc;
}

// ============================================================
// Kernel 1: W_eff = W + up @ down, written as fp16 hi/lo pair
// ============================================================
__global__ void k_weff(const float* __restrict__ Wq, const float* __restrict__ Wk,
                       const float* __restrict__ Wv, const float* __restrict__ Wo)
{
    const int per_w = DD * DD / 4;
    int idx = blockIdx.x * blockDim.x + threadIdx.x;
    if (idx >= 4 * per_w) return;
    int w = idx / per_w;
    int e4 = idx - w * per_w;
    int o = e4 / (DD / 4);
    int i4 = e4 - o * (DD / 4);
    const float* Ws[4] = {Wq, Wk, Wv, Wo};
    float4 acc = reinterpret_cast<const float4*>(Ws[w])[e4];
#pragma unroll
    for (int r = 0; r < RK; r++) {
        float u = g_up[w][o * RK + r];
        float4 d = reinterpret_cast<const float4*>(&g_down[w][r * DD])[i4];
        acc.x += u * d.x; acc.y += u * d.y; acc.z += u * d.z; acc.w += u * d.w;
    }
    float v[4] = {acc.x, acc.y, acc.z, acc.w};
    reinterpret_cast<uint32_t*>(&g_Whi[w][0])[2*e4]   = pack2(v[0], v[1]);
    reinterpret_cast<uint32_t*>(&g_Whi[w][0])[2*e4+1] = pack2(v[2], v[3]);
    reinterpret_cast<uint32_t*>(&g_Wlo[w][0])[2*e4]   = pack2(res_lo(v[0]), res_lo(v[1]));
    reinterpret_cast<uint32_t*>(&g_Wlo[w][0])[2*e4+1] = pack2(res_lo(v[2]), res_lo(v[3]));
}

// ============================================================
// Kernel 1b: fp32 activation -> fp16 hi only
// ============================================================
__global__ void k_cvtA(const float* __restrict__ src)
{
    int i = blockIdx.x * blockDim.x + threadIdx.x;
    if (i >= NTOK * DD / 4) return;
    float4 a = reinterpret_cast<const float4*>(src)[i];
    reinterpret_cast<uint32_t*>(g_Ah)[2*i]   = pack2(a.x, a.y);
    reinterpret_cast<uint32_t*>(g_Ah)[2*i+1] = pack2(a.z, a.w);
}

// ============================================================
// GEMM core A: 128x128 CTA tile, BK=32, 8 warps x (32x64),
// 256 threads, 3-stage pipeline, 1 sync/chunk. (R15, unchanged)
// ============================================================
#define BK 32
#define TSTRIDE 80
#define TILEB (128 * TSTRIDE)
#define STAGEB (3 * TILEB)         // Ah, Wh, Wl
#define GEMM_SMEM (3 * STAGEB)     // 3 pipeline stages = 92160
#define NCHUNK (DD / BK)

struct GemmOut {
    float* Cf; const float* bias;
    __half* Ch; __half* Cl;        // Cl may be null (hi-only output)
};

__device__ __forceinline__ void gemm_body(
    const __half* __restrict__ Ah, const __half* __restrict__ Whi,
    const __half* __restrict__ Wlo,
    const GemmOut& o, size_t tileM, size_t tileN, char* smem)
{
    const uint32_t sbase = smem_u32(smem);
    const int tid = threadIdx.x;
    const int lane = tid & 31, wid = tid >> 5;        // 8 warps
    const int warp_m = (wid & 3) * 32, warp_n = (wid >> 2) * 64;
    const int K = DD, N = DD;

    const __half* srcs[3] = {Ah, Whi, Wlo};

    auto load_stage = [&](int kc, int s) {
        const int kcol = kc * BK;
        uint32_t dst0 = sbase + s * STAGEB;
#pragma unroll
        for (int i = 0; i < 6; i++) {
            int idx = i * 256 + tid;
            int t = idx >> 9;
            int rem = idx & 511;
            int r = rem >> 2, c = rem & 3;
            size_t grow = (t == 0) ? (tileM + r) : (tileN + r);
            const __half* src = srcs[t] + grow * K + kcol + c * 8;
            cp16(dst0 + t * TILEB + r * TSTRIDE + c * 16, src);
        }
        CP_COMMIT();
    };

    float acc[2][8][4];
#pragma unroll
    for (int mf = 0; mf < 2; mf++)
#pragma unroll
        for (int nf = 0; nf < 8; nf++)
#pragma unroll
            for (int j = 0; j < 4; j++) acc[mf][nf][j] = 0.f;

    load_stage(0, 0);
    load_stage(1, 1);

    const int a_row = warp_m + ((lane >> 3) & 1) * 8 + (lane & 7);
    const uint32_t a_off = (uint32_t)(a_row * TSTRIDE + (lane >> 4) * 16);
    const int b_row = warp_n + ((lane >> 4) & 1) * 8 + (lane & 7);
    const uint32_t b_off = (uint32_t)(b_row * TSTRIDE + ((lane >> 3) & 1) * 16);

    for (int kc = 0; kc < NCHUNK; kc++) {
        CP_WAIT(1);
        __syncthreads();

        const uint32_t stage = sbase + (uint32_t)(kc % 3) * STAGEB;
#pragma unroll
        for (int ks = 0; ks < 2; ks++) {
            const uint32_t kb = ks * 32;
            uint32_t ah[2][4];
#pragma unroll
            for (int mf = 0; mf < 2; mf++)
                ldsm4(ah[mf], stage + a_off + mf * (16 * TSTRIDE) + kb);
#pragma unroll
            for (int np = 0; np < 4; np++) {
                uint32_t bh[4], bl[4];
                ldsm4(bh, stage + TILEB + b_off + np * (16 * TSTRIDE) + kb);
                ldsm4(bl, stage + 2 * TILEB + b_off + np * (16 * TSTRIDE) + kb);
#pragma unroll
                for (int mf = 0; mf < 2; mf++)
#pragma unroll
                    for (int half = 0; half < 2; half++)
                        mma16816(acc[mf][np * 2 + half], ah[mf], bh + half * 2);
#pragma unroll
                for (int mf = 0; mf < 2; mf++)
#pragma unroll
                    for (int half = 0; half < 2; half++)
                        mma16816(acc[mf][np * 2 + half], ah[mf], bl + half * 2);
            }
        }
        if (kc + 2 < NCHUNK) load_stage(kc + 2, (kc + 2) % 3);
    }

    const int er = lane >> 2;
    const int ec = (lane & 3) * 2;
#pragma unroll
    for (int mf = 0; mf < 2; mf++) {
        size_t row0 = tileM + warp_m + mf * 16 + er;
#pragma unroll
        for (int nf = 0; nf < 8; nf++) {
            size_t col = tileN + warp_n + nf * 8 + ec;
            float f0 = acc[mf][nf][0], f1 = acc[mf][nf][1];
            float f2 = acc[mf][nf][2], f3 = acc[mf][nf][3];
            if (o.Cf) {
                float bx = 0.f, by = 0.f;
                if (o.bias) { bx = o.bias[col]; by = o.bias[col + 1]; }
                float2 v0 = {f0 + bx, f1 + by};
                float2 v1 = {f2 + bx, f3 + by};
                *reinterpret_cast<float2*>(o.Cf + row0 * N + col) = v0;
                *reinterpret_cast<float2*>(o.Cf + (row0 + 8) * N + col) = v1;
            } else {
                *reinterpret_cast<uint32_t*>(o.Ch + row0 * N + col)       = pack2(f0, f1);
                *reinterpret_cast<uint32_t*>(o.Ch + (row0 + 8) * N + col) = pack2(f2, f3);
                if (o.Cl) {
                    *reinterpret_cast<uint32_t*>(o.Cl + row0 * N + col)       = pack2(res_lo(f0), res_lo(f1));
                    *reinterpret_cast<uint32_t*>(o.Cl + (row0 + 8) * N + col) = pack2(res_lo(f2), res_lo(f3));
                }
            }
        }
    }
}

// ---- fused QKV: grid (N/128, M/128, 3); z selects weight/output ----
__global__ void __launch_bounds__(256, 2) qkv_tc()
{
    extern __shared__ char smem[];
    const int z = blockIdx.z;
    GemmOut o;
    o.Cf = nullptr; o.bias = nullptr;
    o.Ch = (z == 0) ? g_Qh : (z == 1) ? g_Kh : g_Vh;
    o.Cl = (z == 0) ? nullptr : (z == 1) ? g_Kl : g_Vl;
    gemm_body(g_Ah, g_Whi[z], g_Wlo[z],
              o, (size_t)blockIdx.y * 128, (size_t)blockIdx.x * 128, smem);
}

// ============================================================
// GEMM core B (o_tc): 64x128 CTA tile, 128 threads, 4 warps
// of the SAME 32x64 microkernel, 2-stage, 3 CTAs/SM.
// Better wave quantization for the 640-tile output GEMM.
// ============================================================
#define TILEB64_A (64 * TSTRIDE)           // 5120
#define STAGEB64 (TILEB64_A + 2 * TILEB)   // 25600
#define GEMM64_SMEM (2 * STAGEB64)         // 51200

__global__ void __launch_bounds__(128, 3) o_tc(const float* __restrict__ bias,
                                               float* __restrict__ out)
{
    extern __shared__ char smem[];
    const uint32_t sbase = smem_u32(smem);
    const int tid = threadIdx.x;
    const int lane = tid & 31, wid = tid >> 5;        // 4 warps
    const int warp_m = (wid & 1) * 32, warp_n = (wid >> 1) * 64;
    const int K = DD, N = DD;
    const size_t tileM = (size_t)blockIdx.y * 64;
    const size_t tileN = (size_t)blockIdx.x * 128;

    auto load_stage = [&](int kc, int s) {
        const int kcol = kc * BK;
        uint32_t dst0 = sbase + s * STAGEB64;
#pragma unroll
        for (int i = 0; i < 10; i++) {
            int idx = i * 128 + tid;          // 0..1279
            const __half* src; uint32_t d;
            if (idx < 256) {                  // A: 64 rows x 4 chunks (i<2, uniform)
                int r = idx >> 2, c = idx & 3;
                src = g_AOh + (tileM + r) * K + kcol + c * 8;
                d = dst0 + r * TSTRIDE + c * 16;
            } else {                          // Wh then Wl: 128 rows x 4 chunks each
                int j = idx - 256;
                int t = j >> 9;
                int rem = j & 511;
                int r = rem >> 2, c = rem & 3;
                src = (t ? g_Wlo[3] : g_Whi[3]) + (tileN + r) * K + kcol + c * 8;
                d = dst0 + TILEB64_A + t * TILEB + r * TSTRIDE + c * 16;
            }
            cp16(d, src);
        }
        CP_COMMIT();
    };

    float acc[2][8][4];
#pragma unroll
    for (int mf = 0; mf < 2; mf++)
#pragma unroll
        for (int nf = 0; nf < 8; nf++)
#pragma unroll
            for (int j = 0; j < 4; j++) acc[mf][nf][j] = 0.f;

    load_stage(0, 0);

    const int a_row = warp_m + ((lane >> 3) & 1) * 8 + (lane & 7);
    const uint32_t a_off = (uint32_t)(a_row * TSTRIDE + (lane >> 4) * 16);
    const int b_row = warp_n + ((lane >> 4) & 1) * 8 + (lane & 7);
    const uint32_t b_off = (uint32_t)(b_row * TSTRIDE + ((lane >> 3) & 1) * 16);

    for (int kc = 0; kc < NCHUNK; kc++) {
        const int s = kc & 1;
        if (kc + 1 < NCHUNK) { load_stage(kc + 1, s ^ 1); CP_WAIT(1); }
        else { CP_WAIT(0); }
        __syncthreads();

        const uint32_t stage = sbase + (uint32_t)s * STAGEB64;
#pragma unroll
        for (int ks = 0; ks < 2; ks++) {
            const uint32_t kb = ks * 32;
            uint32_t ah[2][4];
#pragma unroll
            for (int mf = 0; mf < 2; mf++)
                ldsm4(ah[mf], stage + a_off + mf * (16 * TSTRIDE) + kb);
#pragma unroll
            for (int np = 0; np < 4; np++) {
                uint32_t bh[4], bl[4];
                ldsm4(bh, stage + TILEB64_A + b_off + np * (16 * TSTRIDE) + kb);
                ldsm4(bl, stage + TILEB64_A + TILEB + b_off + np * (16 * TSTRIDE) + kb);
#pragma unroll
                for (int mf = 0; mf < 2; mf++)
#pragma unroll
                    for (int half = 0; half < 2; half++)
                        mma16816(acc[mf][np * 2 + half], ah[mf], bh + half * 2);
#pragma unroll
                for (int mf = 0; mf < 2; mf++)
#pragma unroll
                    for (int half = 0; half < 2; half++)
                        mma16816(acc[mf][np * 2 + half], ah[mf], bl + half * 2);
            }
        }
        __syncthreads();
    }

    const int er = lane >> 2;
    const int ec = (lane & 3) * 2;
#pragma unroll
    for (int mf = 0; mf < 2; mf++) {
        size_t row0 = tileM + warp_m + mf * 16 + er;
#pragma unroll
        for (int nf = 0; nf < 8; nf++) {
            size_t col = tileN + warp_n + nf * 8 + ec;
            float bx = bias[col], by = bias[col + 1];
            float2 v0 = {acc[mf][nf][0] + bx, acc[mf][nf][1] + by};
            float2 v1 = {acc[mf][nf][2] + bx, acc[mf][nf][3] + by};
            *reinterpret_cast<float2*>(out + row0 * N + col) = v0;
            *reinterpret_cast<float2*>(out + (row0 + 8) * N + col) = v1;
        }
    }
}

// ============================================================
// Kernel 3: flash attention, 2-pass split fp16 FA2.
// K+V fused into one double-buffered tile group (full tile
// prefetched one iteration ahead); 1 wait + 2 syncs per iter.
// BQ=128, BK=64, hd=160. 8 warps x 16 rows. grid (16, 8, 2).
// ============================================================
#define AQ_ROWB 336                      // 168 halves per row
#define Q_TILEB (128 * AQ_ROWB)          // 43008
#define KV_ARRB (64 * AQ_ROWB)           // 21504 (one of Kh/Kl/Vh/Vl)
#define KV_STAGEB (4 * KV_ARRB)          // 86016
#define ATTN_SMEM (Q_TILEB + 2 * KV_STAGEB)   // 215040

__global__ void __launch_bounds__(256) attn_tc()
{
    extern __shared__ char sm[];
    const uint32_t sb = smem_u32(sm);
    const uint32_t Q_s = sb;
    const uint32_t KV_s = sb + Q_TILEB;   // 2 stages of [Kh][Kl][Vh][Vl]

    const int qt = blockIdx.x, h = blockIdx.y, b = blockIdx.z;
    const int tid = threadIdx.x, lane = tid & 31, wid = tid >> 5;
    const float cscale = rsqrtf((float)HDIM) * 1.44269504f;   // attn_scale * log2(e)

    const size_t qtok = (size_t)b * SEQ + (size_t)qt * 128;
    const size_t hoff = (size_t)h * HDIM;

    auto load_KV = [&](int kt, int s) {
        const size_t ktok = (size_t)b * SEQ + (size_t)kt * 64;
        uint32_t dst = KV_s + (uint32_t)s * KV_STAGEB;
        const __half* gs[4] = {g_Kh, g_Kl, g_Vh, g_Vl};
#pragma unroll
        for (int i = 0; i < 20; i++) {
            int idx = i * 256 + tid;
            int arr = idx / 1280;
            int rem = idx - arr * 1280;
            int r = rem / 20, c = rem - r * 20;
            cp16(dst + arr * KV_ARRB + r * AQ_ROWB + c * 16,
                 gs[arr] + (ktok + r) * DD + hoff + c * 8);
        }
    };

    // ---- prologue: {Q + KV(0)} = group 0, KV(1) = group 1 ----
#pragma unroll
    for (int i = 0; i < 10; i++) {
        int idx = i * 256 + tid;
        int r = idx / 20, c = idx - r * 20;
        cp16(Q_s + r * AQ_ROWB + c * 16, g_Qh + (qtok + r) * DD + hoff + c * 8);
    }
    load_KV(0, 0);
    CP_COMMIT();
    load_KV(1, 1);
    CP_COMMIT();

    float m0 = -1e30f, m1 = -1e30f, l0 = 0.f, l1 = 0.f;
    float oacc[20][4];
#pragma unroll
    for (int v = 0; v < 20; v++)
#pragma unroll
        for (int j = 0; j < 4; j++) oacc[v][j] = 0.f;

    const uint32_t qa_off = (uint32_t)((wid * 16 + (lane & 15)) * AQ_ROWB + (lane >> 4) * 16);
    const uint32_t kb_lane = (uint32_t)((((lane >> 4) & 1) * 8 + (lane & 7)) * AQ_ROWB + ((lane >> 3) & 1) * 16);
    const uint32_t v_lane = (uint32_t)((lane & 15) * AQ_ROWB + (lane >> 4) * 16);

    for (int kt = 0; kt < SEQ / 64; kt++) {
        CP_WAIT(1);                      // KV(kt) (and Q) resident; KV(kt+1) in flight
        __syncthreads();

        const uint32_t Kst = KV_s + (uint32_t)(kt & 1) * KV_STAGEB;

        // ---- S = Q K^T : Qh * (Kh + Kl), hi sweep then lo sweep ----
        float sacc[8][4];
#pragma unroll
        for (int nt = 0; nt < 8; nt++)
#pragma unroll
            for (int j = 0; j < 4; j++) sacc[nt][j] = 0.f;

#pragma unroll
        for (int k = 0; k < 10; k++) {
            uint32_t ah[4];
            ldsm4(ah, Q_s + qa_off + k * 32);
            uint32_t bh[4][4], bl[4][4];
#pragma unroll
            for (int np = 0; np < 4; np++) {
                uint32_t kaddr = Kst + (uint32_t)(np * 16 * AQ_ROWB) + kb_lane + k * 32;
                ldsm4(bh[np], kaddr);
                ldsm4(bl[np], kaddr + KV_ARRB);
            }
#pragma unroll
            for (int np = 0; np < 4; np++)
#pragma unroll
                for (int half = 0; half < 2; half++)
                    mma16816(sacc[np * 2 + half], ah, bh[np] + half * 2);
#pragma unroll
            for (int np = 0; np < 4; np++)
#pragma unroll
                for (int half = 0; half < 2; half++)
                    mma16816(sacc[np * 2 + half], ah, bl[np] + half * 2);
        }

        // ---- online softmax ----
        float mx0 = -1e30f, mx1 = -1e30f;
#pragma unroll
        for (int nt = 0; nt < 8; nt++) {
            sacc[nt][0] *= cscale; sacc[nt][1] *= cscale;
            sacc[nt][2] *= cscale; sacc[nt][3] *= cscale;
            mx0 = fmaxf(mx0, fmaxf(sacc[nt][0], sacc[nt][1]));
            mx1 = fmaxf(mx1, fmaxf(sacc[nt][2], sacc[nt][3]));
        }
        mx0 = fmaxf(mx0, __shfl_xor_sync(0xffffffffu, mx0, 1));
        mx0 = fmaxf(mx0, __shfl_xor_sync(0xffffffffu, mx0, 2));
        mx1 = fmaxf(mx1, __shfl_xor_sync(0xffffffffu, mx1, 1));
        mx1 = fmaxf(mx1, __shfl_xor_sync(0xffffffffu, mx1, 2));
        float nm0 = fmaxf(m0, mx0), nm1 = fmaxf(m1, mx1);
        float al0 = ex2f(m0 - nm0), al1 = ex2f(m1 - nm1);
        m0 = nm0; m1 = nm1;

        float ps0 = 0.f, ps1 = 0.f;
#pragma unroll
        for (int nt = 0; nt < 8; nt++) {
            sacc[nt][0] = ex2f(sacc[nt][0] - nm0);
            sacc[nt][1] = ex2f(sacc[nt][1] - nm0);
            sacc[nt][2] = ex2f(sacc[nt][2] - nm1);
            sacc[nt][3] = ex2f(sacc[nt][3] - nm1);
            ps0 += sacc[nt][0] + sacc[nt][1];
            ps1 += sacc[nt][2] + sacc[nt][3];
        }
        ps0 += __shfl_xor_sync(0xffffffffu, ps0, 1);
        ps0 += __shfl_xor_sync(0xffffffffu, ps0, 2);
        ps1 += __shfl_xor_sync(0xffffffffu, ps1, 1);
        ps1 += __shfl_xor_sync(0xffffffffu, ps1, 2);
        l0 = l0 * al0 + ps0;
        l1 = l1 * al1 + ps1;

#pragma unroll
        for (int v = 0; v < 20; v++) {
            oacc[v][0] *= al0; oacc[v][1] *= al0;
            oacc[v][2] *= al1; oacc[v][3] *= al1;
        }

        // ---- O += P V : same stage (already resident) ----
        const uint32_t Vst = Kst + 2 * KV_ARRB;
#pragma unroll
        for (int kt2 = 0; kt2 < 4; kt2++) {
            const float* p0 = sacc[2 * kt2];
            const float* p1 = sacc[2 * kt2 + 1];
            uint32_t pah[4];
            pah[0] = pack2(p0[0], p0[1]);
            pah[1] = pack2(p0[2], p0[3]);
            pah[2] = pack2(p1[0], p1[1]);
            pah[3] = pack2(p1[2], p1[3]);
#pragma unroll
            for (int vp = 0; vp < 10; vp++) {
                uint32_t bvh[4], bvl[4];
                uint32_t vaddr = Vst + (uint32_t)(kt2 * 16 * AQ_ROWB) + v_lane + vp * 32;
                ldsm4t(bvh, vaddr);
                ldsm4t(bvl, vaddr + KV_ARRB);
                mma16816(oacc[vp * 2 + 0], pah, bvh + 0);
                mma16816(oacc[vp * 2 + 1], pah, bvh + 2);
                mma16816(oacc[vp * 2 + 0], pah, bvl + 0);
                mma16816(oacc[vp * 2 + 1], pah, bvl + 2);
            }
        }
        __syncthreads();                 // all reads of this stage done
        if (kt + 2 < SEQ / 64) load_KV(kt + 2, kt & 1);
        CP_COMMIT();                     // uniform group count (may be empty)
    }

    // ---- epilogue: normalize, store fp16 hi (A-side of o-proj) ----
    float inv0 = 1.f / l0, inv1 = 1.f / l1;
    const size_t tok0 = qtok + wid * 16 + (lane >> 2);
    const size_t tok1 = tok0 + 8;
#pragma unroll
    for (int nt = 0; nt < 20; nt++) {
        size_t col = hoff + nt * 8 + (lane & 3) * 2;
        *reinterpret_cast<uint32_t*>(g_AOh + tok0 * DD + col) = pack2(oacc[nt][0] * inv0, oacc[nt][1] * inv0);
        *reinterpret_cast<uint32_t*>(g_AOh + tok1 * DD + col) = pack2(oacc[nt][2] * inv1, oacc[nt][3] * inv1);
    }
}

// ============================================================
// host launcher
// ============================================================
extern "C" void kernel_launch(void* const* d_in, const int* in_sizes, int n_in,
                              void* d_out, int out_size)
{
    const float* x   = (const float*)d_in[0];
    const float* pal = (const float*)d_in[1];
    const float* Wq  = (const float*)d_in[2];
    const float* Wk  = (const float*)d_in[3];
    const float* Wv  = (const float*)d_in[4];
    const float* Wo  = (const float*)d_in[5];
    const float* bo  = (const float*)d_in[6];
    const float* qd  = (const float*)d_in[7];
    const float* qu  = (const float*)d_in[8];
    const float* kd  = (const float*)d_in[9];
    const float* ku  = (const float*)d_in[10];
    const float* vd  = (const float*)d_in[11];
    const float* vu  = (const float*)d_in[12];
    const float* od  = (const float*)d_in[13];
    const float* ou  = (const float*)d_in[14];
    float* out = (float*)d_out;

    cudaFuncSetAttribute(qkv_tc, cudaFuncAttributeMaxDynamicSharedMemorySize, GEMM_SMEM);
    cudaFuncSetAttribute(o_tc, cudaFuncAttributeMaxDynamicSharedMemorySize, GEMM64_SMEM);
    cudaFuncSetAttribute(attn_tc, cudaFuncAttributeMaxDynamicSharedMemorySize, ATTN_SMEM);

    // 0) palette contractions
    k_downup<<<(8 * RK * DD + 255) / 256, 256>>>(pal, qd, qu, kd, ku, vd, vu, od, ou);
    // 1) effective weights (LoRA folded) -> fp16 hi/lo
    k_weff<<<(4 * DD * DD / 4 + 255) / 256, 256>>>(Wq, Wk, Wv, Wo);
    // 1b) x -> fp16 hi
    k_cvtA<<<(NTOK * DD / 4 + 255) / 256, 256>>>(x);
    // 2) fused Q,K,V projections (one launch, 960 CTAs of 256 thr)
    dim3 gqkv(DD / 128, NTOK / 128, 3);
    qkv_tc<<<gqkv, 256, GEMM_SMEM>>>();
    // 3) attention (fused-KV double buffer) -> fp16 hi AO
    dim3 gattn(SEQ / 128, NH, NB);
    attn_tc<<<gattn, 256, ATTN_SMEM>>>();
    // 4) output projection + bias (64x128 tiles, 640 CTAs, 3/SM)
    dim3 go(DD / 128, NTOK / 64);
    o_tc<<<go, 128, GEMM64_SMEM>>>(bo, out);
}